// round 11
// baseline (speedup 1.0000x reference)
#include <cuda_runtime.h>
#include <cuda_bf16.h>
#include <math_constants.h>

#define RANGE_MIN    (-5.0f)
#define RANGE_MAX    ( 5.0f)
#define MIN_BIN_SIZE (0.0001f)
#define MIN_SLOPE    (0.0001f)
#define KBINS        8
#define NCELLS       4096
#define CELL_SCALE   (NCELLS / (RANGE_MAX - RANGE_MIN))   // 409.6

__device__ __forceinline__ float softplusf(float z) {
    return (z > 20.0f) ? z : log1pf(expf(z));
}

struct Tables {
    float4 tab[2 * KBINS];      // {x_k, inv_w, y_k, h | s_k, s_k1, s, d2}
    float  ikn[KBINS + 2];      // interior knots [1..7], [8],[9] = +INF
    float  misc[2];             // sl0, slK
    float2 lut[NCELLS];         // {knot_next, bin (bitcast int)}
};

__device__ __forceinline__ void rqs_eval(
    float x, const Tables& T, float sl0, float slK,
    float& y_o, float& ld_o)
{
    float xc = fminf(fmaxf(x, RANGE_MIN), RANGE_MAX);

    // cell -> candidate bin -> single correction
    int c = (int)fmaf(xc, CELL_SCALE, (float)(NCELLS / 2));
    c = min(c, NCELLS - 1);                 // xc >= -5 guarantees c >= 0
    float2 rec = T.lut[c];
    int b = __float_as_int(rec.y) + (xc >= rec.x);

    float4 A = T.tab[2 * b];       // x_k, inv_w, y_k, h
    float4 B = T.tab[2 * b + 1];   // s_k, s_k1, s, d2

    float xi = (xc - A.x) * A.y;
    xi = fminf(fmaxf(xi, 0.0f), 1.0f);

    float xi1m = 1.0f - xi;
    float t    = xi * xi1m;
    float xi2  = xi * xi;

    float num  = B.z * xi2 + B.x * t;
    float den  = fmaf(B.w, t, B.z);
    float rden = __fdividef(1.0f, den);

    float y_spline = fmaf(A.w * num, rden, A.z);

    float numd  = B.z * B.z * (B.y * xi2 + 2.0f * B.z * t + B.x * xi1m * xi1m);
    float deriv = numd * rden * rden;
    // At clamped endpoints deriv == slopes[0] / slopes[K] exactly, so this
    // logdet is also correct for the out-of-range linear branches.
    ld_o = __logf(deriv);

    bool below = x < RANGE_MIN;
    bool above = x > RANGE_MAX;
    float y_lin_l = fmaf(x - RANGE_MIN, sl0, RANGE_MIN);
    float y_lin_r = fmaf(x - RANGE_MAX, slK, RANGE_MAX);

    y_o = below ? y_lin_l : (above ? y_lin_r : y_spline);
}

__global__ void __launch_bounds__(256, 5) rqs_kernel(
    const float* __restrict__ x_in,
    const float* __restrict__ params,
    float* __restrict__ y_out,
    float* __restrict__ ld_out,
    int n)
{
    __shared__ Tables T;

    if (threadIdx.x == 0) {
        float w[KBINS], h[KBINS], sl[KBINS + 1];
        const float total = RANGE_MAX - RANGE_MIN;
        const float scale = total - KBINS * MIN_BIN_SIZE;

        float m = -1e30f;
        #pragma unroll
        for (int i = 0; i < KBINS; i++) m = fmaxf(m, params[i]);
        float sum = 0.0f;
        #pragma unroll
        for (int i = 0; i < KBINS; i++) { w[i] = expf(params[i] - m); sum += w[i]; }
        float inv = 1.0f / sum;
        #pragma unroll
        for (int i = 0; i < KBINS; i++) w[i] = w[i] * inv * scale + MIN_BIN_SIZE;

        m = -1e30f;
        #pragma unroll
        for (int i = 0; i < KBINS; i++) m = fmaxf(m, params[KBINS + i]);
        sum = 0.0f;
        #pragma unroll
        for (int i = 0; i < KBINS; i++) { h[i] = expf(params[KBINS + i] - m); sum += h[i]; }
        inv = 1.0f / sum;
        #pragma unroll
        for (int i = 0; i < KBINS; i++) h[i] = h[i] * inv * scale + MIN_BIN_SIZE;

        const float off = logf(expf(1.0f - MIN_SLOPE) - 1.0f);
        #pragma unroll
        for (int i = 0; i < KBINS + 1; i++)
            sl[i] = softplusf(params[2 * KBINS + i] + off) + MIN_SLOPE;

        float xpos[KBINS + 1], ypos[KBINS + 1];
        xpos[0] = RANGE_MIN; ypos[0] = RANGE_MIN;
        float cx = 0.0f, cy = 0.0f;
        #pragma unroll
        for (int i = 0; i < KBINS; i++) {
            cx += w[i]; cy += h[i];
            xpos[i + 1] = cx + RANGE_MIN;
            ypos[i + 1] = cy + RANGE_MIN;
        }

        #pragma unroll
        for (int b = 0; b < KBINS; b++) {
            float width  = xpos[b + 1] - xpos[b];
            float height = ypos[b + 1] - ypos[b];
            float inv_w  = 1.0f / width;
            float s      = height * inv_w;
            T.tab[2 * b]     = make_float4(xpos[b], inv_w, ypos[b], height);
            T.tab[2 * b + 1] = make_float4(sl[b], sl[b + 1], s, sl[b] + sl[b + 1] - 2.0f * s);
        }

        #pragma unroll
        for (int j = 1; j < KBINS; j++) T.ikn[j] = xpos[j];
        T.ikn[0]         = -CUDART_INF_F;
        T.ikn[KBINS]     =  CUDART_INF_F;
        T.ikn[KBINS + 1] =  CUDART_INF_F;

        T.misc[0] = sl[0];
        T.misc[1] = sl[KBINS];
    }
    __syncthreads();

    // parallel merged-LUT build: per cell, bin of lower edge + next knot
    {
        float k1 = T.ikn[1], k2 = T.ikn[2], k3 = T.ikn[3], k4 = T.ikn[4],
              k5 = T.ikn[5], k6 = T.ikn[6], k7 = T.ikn[7];
        for (int c = threadIdx.x; c < NCELLS; c += blockDim.x) {
            float cs = RANGE_MIN + (float)c * ((RANGE_MAX - RANGE_MIN) / NCELLS);
            int b0 = 0;
            b0 += (cs >= k1); b0 += (cs >= k2); b0 += (cs >= k3); b0 += (cs >= k4);
            b0 += (cs >= k5); b0 += (cs >= k6); b0 += (cs >= k7);
            T.lut[c] = make_float2(T.ikn[b0 + 1], __int_as_float(b0));
        }
    }
    __syncthreads();

    const float sl0 = T.misc[0];
    const float slK = T.misc[1];

    const int n4 = n >> 2;
    const float4* __restrict__ x4 = (const float4*)x_in;
    float4* __restrict__ y4 = (float4*)y_out;
    float4* __restrict__ l4 = (float4*)ld_out;

    const int stride = gridDim.x * blockDim.x;
    int idx = blockIdx.x * blockDim.x + threadIdx.x;

    for (; idx + stride < n4; idx += 2 * stride) {
        float4 xa = __ldcs(&x4[idx]);
        float4 xb = __ldcs(&x4[idx + stride]);

        float4 ya, la, yb, lb;
        rqs_eval(xa.x, T, sl0, slK, ya.x, la.x);
        rqs_eval(xa.y, T, sl0, slK, ya.y, la.y);
        rqs_eval(xa.z, T, sl0, slK, ya.z, la.z);
        rqs_eval(xa.w, T, sl0, slK, ya.w, la.w);

        __stcs(&y4[idx], ya);
        __stcs(&l4[idx], la);

        rqs_eval(xb.x, T, sl0, slK, yb.x, lb.x);
        rqs_eval(xb.y, T, sl0, slK, yb.y, lb.y);
        rqs_eval(xb.z, T, sl0, slK, yb.z, lb.z);
        rqs_eval(xb.w, T, sl0, slK, yb.w, lb.w);

        __stcs(&y4[idx + stride], yb);
        __stcs(&l4[idx + stride], lb);
    }
    for (; idx < n4; idx += stride) {
        float4 xa = __ldcs(&x4[idx]);
        float4 ya, la;
        rqs_eval(xa.x, T, sl0, slK, ya.x, la.x);
        rqs_eval(xa.y, T, sl0, slK, ya.y, la.y);
        rqs_eval(xa.z, T, sl0, slK, ya.z, la.z);
        rqs_eval(xa.w, T, sl0, slK, ya.w, la.w);
        __stcs(&y4[idx], ya);
        __stcs(&l4[idx], la);
    }
}

extern "C" void kernel_launch(void* const* d_in, const int* in_sizes, int n_in,
                              void* d_out, int out_size) {
    const float* x      = (const float*)d_in[0];
    const float* params = (const float*)d_in[1];
    int n = in_sizes[0];
    float* y  = (float*)d_out;
    float* ld = (float*)d_out + n;

    const int threads = 256;
    int n4 = n >> 2;
    int blocks = (n4 + threads * 8 - 1) / (threads * 8);   // 8 float4 per thread
    if (blocks < 1) blocks = 1;
    rqs_kernel<<<blocks, threads>>>(x, params, y, ld, n);
}

// round 12
// speedup vs baseline: 1.1416x; 1.1416x over previous
#include <cuda_runtime.h>
#include <cuda_bf16.h>
#include <math_constants.h>

#define RANGE_MIN    (-5.0f)
#define RANGE_MAX    ( 5.0f)
#define MIN_BIN_SIZE (0.0001f)
#define MIN_SLOPE    (0.0001f)
#define KBINS        8
#define NCELLS       512
#define CELL_SCALE   (NCELLS / (RANGE_MAX - RANGE_MIN))   // 51.2

__device__ __forceinline__ float softplusf(float z) {
    return (z > 20.0f) ? z : log1pf(expf(z));
}

struct Tables {
    float4 tabA[KBINS];         // {x_k, inv_w, y_k, h}
    float2 tabB[KBINS];         // {s_k, s_k1}
    float2 knotpair[KBINS];     // {knot[b+1], knot[b+2]} (+INF padded)
    float  ikn[KBINS + 2];
    float  misc[4];             // sl0, slK, ld_left, ld_right
    unsigned char lut[NCELLS];  // cell -> bin of cell lower edge
};

__device__ __forceinline__ void rqs_eval(
    float x, const Tables& T,
    float sl0, float slK, float ld_left, float ld_right,
    float& y_o, float& ld_o)
{
    // cell -> candidate bin -> <=2 corrections (clustered smem reads -> broadcast)
    int c = (int)fmaf(x, CELL_SCALE, (float)(NCELLS / 2));
    c = min(max(c, 0), NCELLS - 1);
    int b = (int)T.lut[c];
    float2 kk = T.knotpair[b];
    b += (x >= kk.x);
    b += (x >= kk.y);

    float4 A = T.tabA[b];      // x_k, inv_w, y_k, h
    float2 B = T.tabB[b];      // s_k, s_k1

    float s  = A.w * A.y;                       // h * inv_w
    float d2 = fmaf(-2.0f, s, B.x + B.y);       // s_k + s_k1 - 2s

    float xi = (x - A.x) * A.y;
    xi = fminf(fmaxf(xi, 0.0f), 1.0f);

    float xi1m = 1.0f - xi;
    float t    = xi * xi1m;
    float xi2  = xi * xi;

    float num  = s * xi2 + B.x * t;
    float den  = fmaf(d2, t, s);
    float rden = __fdividef(1.0f, den);

    float y_spline = fmaf(A.w * num, rden, A.z);

    float numd  = s * s * (B.y * xi2 + 2.0f * s * t + B.x * xi1m * xi1m);
    float deriv = numd * rden * rden;
    float ld_spline = __logf(deriv);

    bool below = x < RANGE_MIN;
    bool above = x > RANGE_MAX;

    float y_lin_l = fmaf(x - RANGE_MIN, sl0, RANGE_MIN);
    float y_lin_r = fmaf(x - RANGE_MAX, slK, RANGE_MAX);

    y_o  = below ? y_lin_l : (above ? y_lin_r : y_spline);
    ld_o = below ? ld_left : (above ? ld_right : ld_spline);
}

__device__ __forceinline__ void eval_quad(
    const float4& xv, const Tables& T,
    float sl0, float slK, float ld_left, float ld_right,
    float4& yv, float4& lv)
{
    rqs_eval(xv.x, T, sl0, slK, ld_left, ld_right, yv.x, lv.x);
    rqs_eval(xv.y, T, sl0, slK, ld_left, ld_right, yv.y, lv.y);
    rqs_eval(xv.z, T, sl0, slK, ld_left, ld_right, yv.z, lv.z);
    rqs_eval(xv.w, T, sl0, slK, ld_left, ld_right, yv.w, lv.w);
}

__global__ void __launch_bounds__(256, 5) rqs_kernel(
    const float* __restrict__ x_in,
    const float* __restrict__ params,
    float* __restrict__ y_out,
    float* __restrict__ ld_out,
    int n)
{
    __shared__ Tables T;

    if (threadIdx.x == 0) {
        float w[KBINS], h[KBINS], sl[KBINS + 1];
        const float total = RANGE_MAX - RANGE_MIN;
        const float scale = total - KBINS * MIN_BIN_SIZE;

        float m = -1e30f;
        #pragma unroll
        for (int i = 0; i < KBINS; i++) m = fmaxf(m, params[i]);
        float sum = 0.0f;
        #pragma unroll
        for (int i = 0; i < KBINS; i++) { w[i] = expf(params[i] - m); sum += w[i]; }
        float inv = 1.0f / sum;
        #pragma unroll
        for (int i = 0; i < KBINS; i++) w[i] = w[i] * inv * scale + MIN_BIN_SIZE;

        m = -1e30f;
        #pragma unroll
        for (int i = 0; i < KBINS; i++) m = fmaxf(m, params[KBINS + i]);
        sum = 0.0f;
        #pragma unroll
        for (int i = 0; i < KBINS; i++) { h[i] = expf(params[KBINS + i] - m); sum += h[i]; }
        inv = 1.0f / sum;
        #pragma unroll
        for (int i = 0; i < KBINS; i++) h[i] = h[i] * inv * scale + MIN_BIN_SIZE;

        const float off = logf(expf(1.0f - MIN_SLOPE) - 1.0f);
        #pragma unroll
        for (int i = 0; i < KBINS + 1; i++)
            sl[i] = softplusf(params[2 * KBINS + i] + off) + MIN_SLOPE;

        float xpos[KBINS + 1], ypos[KBINS + 1];
        xpos[0] = RANGE_MIN; ypos[0] = RANGE_MIN;
        float cx = 0.0f, cy = 0.0f;
        #pragma unroll
        for (int i = 0; i < KBINS; i++) {
            cx += w[i]; cy += h[i];
            xpos[i + 1] = cx + RANGE_MIN;
            ypos[i + 1] = cy + RANGE_MIN;
        }

        #pragma unroll
        for (int b = 0; b < KBINS; b++) {
            float width  = xpos[b + 1] - xpos[b];
            float height = ypos[b + 1] - ypos[b];
            float inv_w  = 1.0f / width;
            T.tabA[b] = make_float4(xpos[b], inv_w, ypos[b], height);
            T.tabB[b] = make_float2(sl[b], sl[b + 1]);
        }

        #pragma unroll
        for (int j = 1; j < KBINS; j++) T.ikn[j] = xpos[j];
        T.ikn[KBINS]     = CUDART_INF_F;
        T.ikn[KBINS + 1] = CUDART_INF_F;
        #pragma unroll
        for (int b = 0; b < KBINS; b++)
            T.knotpair[b] = make_float2(T.ikn[b + 1], T.ikn[b + 2]);

        T.misc[0] = sl[0];
        T.misc[1] = sl[KBINS];
        T.misc[2] = logf(sl[0]);
        T.misc[3] = logf(sl[KBINS]);
    }
    __syncthreads();

    {
        float k1 = T.ikn[1], k2 = T.ikn[2], k3 = T.ikn[3], k4 = T.ikn[4],
              k5 = T.ikn[5], k6 = T.ikn[6], k7 = T.ikn[7];
        for (int c = threadIdx.x; c < NCELLS; c += blockDim.x) {
            float cs = RANGE_MIN + (float)c * ((RANGE_MAX - RANGE_MIN) / NCELLS);
            int b = 0;
            b += (cs >= k1); b += (cs >= k2); b += (cs >= k3); b += (cs >= k4);
            b += (cs >= k5); b += (cs >= k6); b += (cs >= k7);
            T.lut[c] = (unsigned char)b;
        }
    }
    __syncthreads();

    const float sl0      = T.misc[0];
    const float slK      = T.misc[1];
    const float ld_left  = T.misc[2];
    const float ld_right = T.misc[3];

    const int n4 = n >> 2;
    const float4* __restrict__ x4 = (const float4*)x_in;
    float4* __restrict__ y4 = (float4*)y_out;
    float4* __restrict__ l4 = (float4*)ld_out;

    const int stride = gridDim.x * blockDim.x;
    int idx = blockIdx.x * blockDim.x + threadIdx.x;

    // main loop: 4 independent float4 loads in flight
    for (; idx + 3 * stride < n4; idx += 4 * stride) {
        float4 xa = __ldcs(&x4[idx]);
        float4 xb = __ldcs(&x4[idx + stride]);
        float4 xc = __ldcs(&x4[idx + 2 * stride]);
        float4 xd = __ldcs(&x4[idx + 3 * stride]);

        float4 yv, lv;
        eval_quad(xa, T, sl0, slK, ld_left, ld_right, yv, lv);
        __stcs(&y4[idx], yv);
        __stcs(&l4[idx], lv);

        eval_quad(xb, T, sl0, slK, ld_left, ld_right, yv, lv);
        __stcs(&y4[idx + stride], yv);
        __stcs(&l4[idx + stride], lv);

        eval_quad(xc, T, sl0, slK, ld_left, ld_right, yv, lv);
        __stcs(&y4[idx + 2 * stride], yv);
        __stcs(&l4[idx + 2 * stride], lv);

        eval_quad(xd, T, sl0, slK, ld_left, ld_right, yv, lv);
        __stcs(&y4[idx + 3 * stride], yv);
        __stcs(&l4[idx + 3 * stride], lv);
    }
    // tail
    for (; idx < n4; idx += stride) {
        float4 xa = __ldcs(&x4[idx]);
        float4 yv, lv;
        eval_quad(xa, T, sl0, slK, ld_left, ld_right, yv, lv);
        __stcs(&y4[idx], yv);
        __stcs(&l4[idx], lv);
    }
}

extern "C" void kernel_launch(void* const* d_in, const int* in_sizes, int n_in,
                              void* d_out, int out_size) {
    const float* x      = (const float*)d_in[0];
    const float* params = (const float*)d_in[1];
    int n = in_sizes[0];
    float* y  = (float*)d_out;
    float* ld = (float*)d_out + n;

    const int threads = 256;
    int n4 = n >> 2;
    int blocks = (n4 + threads * 8 - 1) / (threads * 8);   // 8 float4 per thread
    if (blocks < 1) blocks = 1;
    rqs_kernel<<<blocks, threads>>>(x, params, y, ld, n);
}

// round 13
// speedup vs baseline: 1.2210x; 1.0696x over previous
#include <cuda_runtime.h>
#include <cuda_bf16.h>
#include <math_constants.h>

#define RANGE_MIN    (-5.0f)
#define RANGE_MAX    ( 5.0f)
#define MIN_BIN_SIZE (0.0001f)
#define MIN_SLOPE    (0.0001f)
#define KBINS        8
#define NCELLS       512
#define CELL_SCALE   (NCELLS / (RANGE_MAX - RANGE_MIN))   // 51.2

__device__ __forceinline__ float softplusf(float z) {
    return (z > 20.0f) ? z : log1pf(expf(z));
}

struct Tables {
    float4 tabA[KBINS];         // {x_k, inv_w, y_k, h}
    float2 tabB[KBINS];         // {s_k, s_k1}
    float2 knotpair[KBINS];     // {knot[b+1], knot[b+2]} (+INF padded)
    float  ikn[KBINS + 2];
    unsigned char lut[NCELLS];  // cell -> bin of cell lower edge
};

__device__ __forceinline__ void rqs_eval(
    float x, const Tables& T, float& y_o, float& ld_o)
{
    // Clamp into spline range. At the clamped endpoints the spline formula
    // reproduces the boundary value and boundary slope EXACTLY, so the
    // out-of-range linear branches reduce to one extrapolation fma below.
    float xc = fminf(fmaxf(x, RANGE_MIN), RANGE_MAX);

    // cell -> candidate bin -> <=2 corrections (clustered smem -> broadcast)
    int c = (int)fmaf(xc, CELL_SCALE, (float)(NCELLS / 2));
    c = min(c, NCELLS - 1);              // xc >= -5 guarantees c >= 0
    int b = (int)T.lut[c];
    float2 kk = T.knotpair[b];
    b += (xc >= kk.x);
    b += (xc >= kk.y);

    float4 A = T.tabA[b];      // x_k, inv_w, y_k, h
    float2 B = T.tabB[b];      // s_k, s_k1

    float s  = A.w * A.y;                       // h * inv_w
    float d2 = fmaf(-2.0f, s, B.x + B.y);       // s_k + s_k1 - 2s

    float xi = (xc - A.x) * A.y;
    xi = fminf(fmaxf(xi, 0.0f), 1.0f);

    float xi1m = 1.0f - xi;
    float t    = xi * xi1m;
    float xi2  = xi * xi;

    float num  = s * xi2 + B.x * t;
    float den  = fmaf(d2, t, s);
    float rden = __fdividef(1.0f, den);

    float y_spline = fmaf(A.w * num, rden, A.z);

    float numd  = s * s * (B.y * xi2 + 2.0f * s * t + B.x * xi1m * xi1m);
    float deriv = numd * rden * rden;

    // logdet: deriv equals the boundary slope at clamped endpoints,
    // so this single log covers all three reference branches.
    ld_o = __logf(deriv);

    // y: linear extrapolation with boundary slope; x - xc == 0 in range.
    y_o = fmaf(x - xc, deriv, y_spline);
}

__device__ __forceinline__ void eval_quad(
    const float4& xv, const Tables& T, float4& yv, float4& lv)
{
    rqs_eval(xv.x, T, yv.x, lv.x);
    rqs_eval(xv.y, T, yv.y, lv.y);
    rqs_eval(xv.z, T, yv.z, lv.z);
    rqs_eval(xv.w, T, yv.w, lv.w);
}

__global__ void __launch_bounds__(256, 5) rqs_kernel(
    const float* __restrict__ x_in,
    const float* __restrict__ params,
    float* __restrict__ y_out,
    float* __restrict__ ld_out,
    int n)
{
    __shared__ Tables T;

    if (threadIdx.x == 0) {
        float w[KBINS], h[KBINS], sl[KBINS + 1];
        const float total = RANGE_MAX - RANGE_MIN;
        const float scale = total - KBINS * MIN_BIN_SIZE;

        float m = -1e30f;
        #pragma unroll
        for (int i = 0; i < KBINS; i++) m = fmaxf(m, params[i]);
        float sum = 0.0f;
        #pragma unroll
        for (int i = 0; i < KBINS; i++) { w[i] = expf(params[i] - m); sum += w[i]; }
        float inv = 1.0f / sum;
        #pragma unroll
        for (int i = 0; i < KBINS; i++) w[i] = w[i] * inv * scale + MIN_BIN_SIZE;

        m = -1e30f;
        #pragma unroll
        for (int i = 0; i < KBINS; i++) m = fmaxf(m, params[KBINS + i]);
        sum = 0.0f;
        #pragma unroll
        for (int i = 0; i < KBINS; i++) { h[i] = expf(params[KBINS + i] - m); sum += h[i]; }
        inv = 1.0f / sum;
        #pragma unroll
        for (int i = 0; i < KBINS; i++) h[i] = h[i] * inv * scale + MIN_BIN_SIZE;

        const float off = logf(expf(1.0f - MIN_SLOPE) - 1.0f);
        #pragma unroll
        for (int i = 0; i < KBINS + 1; i++)
            sl[i] = softplusf(params[2 * KBINS + i] + off) + MIN_SLOPE;

        float xpos[KBINS + 1], ypos[KBINS + 1];
        xpos[0] = RANGE_MIN; ypos[0] = RANGE_MIN;
        float cx = 0.0f, cy = 0.0f;
        #pragma unroll
        for (int i = 0; i < KBINS; i++) {
            cx += w[i]; cy += h[i];
            xpos[i + 1] = cx + RANGE_MIN;
            ypos[i + 1] = cy + RANGE_MIN;
        }

        #pragma unroll
        for (int b = 0; b < KBINS; b++) {
            float width  = xpos[b + 1] - xpos[b];
            float height = ypos[b + 1] - ypos[b];
            float inv_w  = 1.0f / width;
            T.tabA[b] = make_float4(xpos[b], inv_w, ypos[b], height);
            T.tabB[b] = make_float2(sl[b], sl[b + 1]);
        }

        #pragma unroll
        for (int j = 1; j < KBINS; j++) T.ikn[j] = xpos[j];
        T.ikn[KBINS]     = CUDART_INF_F;
        T.ikn[KBINS + 1] = CUDART_INF_F;
        #pragma unroll
        for (int b = 0; b < KBINS; b++)
            T.knotpair[b] = make_float2(T.ikn[b + 1], T.ikn[b + 2]);
    }
    __syncthreads();

    {
        float k1 = T.ikn[1], k2 = T.ikn[2], k3 = T.ikn[3], k4 = T.ikn[4],
              k5 = T.ikn[5], k6 = T.ikn[6], k7 = T.ikn[7];
        for (int c = threadIdx.x; c < NCELLS; c += blockDim.x) {
            float cs = RANGE_MIN + (float)c * ((RANGE_MAX - RANGE_MIN) / NCELLS);
            int b = 0;
            b += (cs >= k1); b += (cs >= k2); b += (cs >= k3); b += (cs >= k4);
            b += (cs >= k5); b += (cs >= k6); b += (cs >= k7);
            T.lut[c] = (unsigned char)b;
        }
    }
    __syncthreads();

    const int n4 = n >> 2;
    const float4* __restrict__ x4 = (const float4*)x_in;
    float4* __restrict__ y4 = (float4*)y_out;
    float4* __restrict__ l4 = (float4*)ld_out;

    const int stride = gridDim.x * blockDim.x;
    int idx = blockIdx.x * blockDim.x + threadIdx.x;

    // main loop: 4 independent float4 loads in flight
    for (; idx + 3 * stride < n4; idx += 4 * stride) {
        float4 xa = __ldcs(&x4[idx]);
        float4 xb = __ldcs(&x4[idx + stride]);
        float4 xc = __ldcs(&x4[idx + 2 * stride]);
        float4 xd = __ldcs(&x4[idx + 3 * stride]);

        float4 yv, lv;
        eval_quad(xa, T, yv, lv);
        __stcs(&y4[idx], yv);
        __stcs(&l4[idx], lv);

        eval_quad(xb, T, yv, lv);
        __stcs(&y4[idx + stride], yv);
        __stcs(&l4[idx + stride], lv);

        eval_quad(xc, T, yv, lv);
        __stcs(&y4[idx + 2 * stride], yv);
        __stcs(&l4[idx + 2 * stride], lv);

        eval_quad(xd, T, yv, lv);
        __stcs(&y4[idx + 3 * stride], yv);
        __stcs(&l4[idx + 3 * stride], lv);
    }
    // tail
    for (; idx < n4; idx += stride) {
        float4 xa = __ldcs(&x4[idx]);
        float4 yv, lv;
        eval_quad(xa, T, yv, lv);
        __stcs(&y4[idx], yv);
        __stcs(&l4[idx], lv);
    }
}

extern "C" void kernel_launch(void* const* d_in, const int* in_sizes, int n_in,
                              void* d_out, int out_size) {
    const float* x      = (const float*)d_in[0];
    const float* params = (const float*)d_in[1];
    int n = in_sizes[0];
    float* y  = (float*)d_out;
    float* ld = (float*)d_out + n;

    const int threads = 256;
    int n4 = n >> 2;
    int blocks = (n4 + threads * 8 - 1) / (threads * 8);   // 8 float4 per thread
    if (blocks < 1) blocks = 1;
    rqs_kernel<<<blocks, threads>>>(x, params, y, ld, n);
}